// round 15
// baseline (speedup 1.0000x reference)
#include <cuda_runtime.h>
#include <math.h>

#define NTOK 4096          // B*T
#define TT   1024
#define Fc   6144          // SW*FB = 96*64
#define EMBc 512

typedef unsigned long long u64;

// ---------------- packed f32x2 helpers (FFMA2 path) -------------------------
__device__ __forceinline__ void fma2(u64 &d, u64 a, u64 b) {
    asm("fma.rn.f32x2 %0, %1, %2, %0;" : "+l"(d) : "l"(a), "l"(b));
}
__device__ __forceinline__ u64 dup2(float x) {
    u64 r; asm("mov.b64 %0, {%1, %1};" : "=l"(r) : "f"(x)); return r;
}
__device__ __forceinline__ float2 up2(u64 v) {
    float2 p; asm("mov.b64 {%0, %1}, %2;" : "=f"(p.x), "=f"(p.y) : "l"(v)); return p;
}
__device__ __forceinline__ float hsum2(u64 v) { float2 p = up2(v); return p.x + p.y; }

// ---------------- cp.async helpers ------------------------------------------
__device__ __forceinline__ void cp16(void* s, const void* g) {
    unsigned sa = (unsigned)__cvta_generic_to_shared(s);
    asm volatile("cp.async.cg.shared.global [%0], [%1], 16;" :: "r"(sa), "l"(g));
}
__device__ __forceinline__ void cp_commit() {
    asm volatile("cp.async.commit_group;");
}
template<int N> __device__ __forceinline__ void cp_wait() {
    asm volatile("cp.async.wait_group %0;" :: "n"(N));
}

// ---------------- scratch ---------------------------------------------------
__device__ float  g_q[(size_t)NTOK * Fc];     // [(n,l), d]
__device__ float  g_kT[(size_t)NTOK * Fc];    // [n][d][m]
__device__ float  g_vT[(size_t)NTOK * Fc];    // [n][d][m]
__device__ float  g_mid[(size_t)NTOK * Fc];   // (B,T,F)
__device__ float  g_emb[(size_t)NTOK * EMBc];
__device__ double g_part[512];                // 256 blocks * 2
__device__ float  g_stats[2];

// ---------------- kernel 1: batched QKV GEMM --------------------------------
#define QKV_SMEM (12416 + 9216)

__global__ __launch_bounds__(512, 2) void qkv_kernel(
    const float* __restrict__ x,
    const float* __restrict__ Wq, const float* __restrict__ bq,
    const float* __restrict__ Wk, const float* __restrict__ bk,
    const float* __restrict__ Wv, const float* __restrict__ bv)
{
    extern __shared__ float sm[];
    float* As = sm;
    float* Ws = sm + 12416;

    const int tid = threadIdx.x;
    const int mat = blockIdx.y;
    const int n0  = blockIdx.x * 2;
    const size_t xbase = (size_t)n0 * Fc;

    const float* W  = (mat == 0) ? Wq : (mat == 1) ? Wk : Wv;
    const float* bi = (mat == 0) ? bq : (mat == 1) ? bk : bv;

    for (int idx = tid; idx < 12288; idx += 512) {
        int d = idx >> 7, m = idx & 127;
        As[idx] = x[xbase + (size_t)(m >> 6) * Fc + d * 64 + (m & 63)];
    }
    for (int idx = tid; idx < 9216; idx += 512) Ws[idx] = W[idx];
    __syncthreads();

    const int r0 = (tid >> 5) * 8;
    const int lane = tid & 31;
    u64 acc[4][3];
    #pragma unroll
    for (int i = 0; i < 4; ++i)
        #pragma unroll
        for (int j = 0; j < 3; ++j) acc[i][j] = 0;

    #pragma unroll 2
    for (int d = 0; d < 96; ++d) {
        ulonglong2 a01 = *(const ulonglong2*)&As[d * 128 + r0];
        ulonglong2 a23 = *(const ulonglong2*)&As[d * 128 + r0 + 4];
        u64 ap[4] = {a01.x, a01.y, a23.x, a23.y};
        u64 w0 = dup2(Ws[d * 96 + lane]);
        u64 w1 = dup2(Ws[d * 96 + lane + 32]);
        u64 w2 = dup2(Ws[d * 96 + lane + 64]);
        #pragma unroll
        for (int i = 0; i < 4; ++i) {
            fma2(acc[i][0], ap[i], w0);
            fma2(acc[i][1], ap[i], w1);
            fma2(acc[i][2], ap[i], w2);
        }
    }
    float bb[3] = {bi[lane], bi[lane + 32], bi[lane + 64]};

    if (mat == 0) {
        #pragma unroll
        for (int i = 0; i < 4; ++i)
            #pragma unroll
            for (int j = 0; j < 3; ++j) {
                float2 p = up2(acc[i][j]);
                int row = r0 + 2 * i, col = lane + 32 * j;
                g_q[xbase + (size_t)row * 96 + col]       = p.x + bb[j];
                g_q[xbase + (size_t)(row + 1) * 96 + col] = p.y + bb[j];
            }
    } else {
        __syncthreads();
        #pragma unroll
        for (int i = 0; i < 4; ++i)
            #pragma unroll
            for (int j = 0; j < 3; ++j) {
                float2 p = up2(acc[i][j]);
                int col = lane + 32 * j, row = r0 + 2 * i;
                As[col * 129 + row]     = p.x + bb[j];
                As[col * 129 + row + 1] = p.y + bb[j];
            }
        __syncthreads();
        float* gout = (mat == 1) ? g_kT : g_vT;
        for (int idx = tid; idx < 12288; idx += 512) {
            int d = idx >> 7, m = idx & 127;
            gout[xbase + (size_t)(m >> 6) * Fc + d * 64 + (m & 63)] = As[d * 129 + m];
        }
    }
}

// ---------------- kernel 2: fused attention + FFN ---------------------------
// phase A smem: sQ 6208 | sKT 6144 | sVT 6144 | sEr 2112 | sS 4096 | sR 4096
// phase B overlays (A's tiles dead): sX@6208 (96x68) | sW@12736 | sH@18880 (64x68)
#define ATT_SMEM 28800

__global__ __launch_bounds__(256, 2) void attn_ffn_kernel(
    const float* __restrict__ Er,
    const float* __restrict__ W1, const float* __restrict__ b1,
    const float* __restrict__ W2, const float* __restrict__ b2)
{
    extern __shared__ float sm[];
    float* sQ  = sm;             // [l*97 + d]
    float* sKT = sm + 6208;      // [d*64 + m]
    float* sVT = sm + 12352;     // [d*64 + m]
    float* sEr = sm + 18496;     // [d*66 + j]
    float* sS  = sm + 20608;     // [l*64 + m]
    float* sR  = sm + 24704;     // [l*64 + j]
    // phase B aliases
    float* sX  = sm + 6208;      // [d*68 + m]
    float* sW  = sm + 12736;     // weight chunk
    float* sH  = sm + 18880;     // [c*68 + m]

    const int tid = threadIdx.x;
    const int n   = blockIdx.x;
    const size_t base = (size_t)n * Fc;

    // ---- vectorized ingest ----
    for (int i4 = tid; i4 < 1536; i4 += 256) {
        float4 v = *(const float4*)&g_q[base + (size_t)i4 * 4];
        int idx = i4 * 4;
        int l = idx / 96, d = idx - l * 96;
        sQ[l * 97 + d]     = v.x;
        sQ[l * 97 + d + 1] = v.y;
        sQ[l * 97 + d + 2] = v.z;
        sQ[l * 97 + d + 3] = v.w;
    }
    for (int i4 = tid; i4 < 1536; i4 += 256)
        *(float4*)&sKT[i4 * 4] = *(const float4*)&g_kT[base + (size_t)i4 * 4];
    for (int i4 = tid; i4 < 1536; i4 += 256)
        *(float4*)&sVT[i4 * 4] = *(const float4*)&g_vT[base + (size_t)i4 * 4];
    for (int idx = tid; idx < 2048; idx += 256) {
        int j = idx >> 5, d = idx & 31;
        sEr[d * 66 + j] = Er[idx];
    }
    __syncthreads();

    const float scale = 0.17677669529663687f;
    const int wid = tid >> 5, lane = tid & 31;
    const int l0 = (tid >> 4) * 4, m0 = (tid & 15) * 4;
    const int d0 = (tid & 15) * 2;

    for (int h = 0; h < 3; ++h) {
        const int hb = h * 32;
        u64 aS[4][2], aR[4][2];
        #pragma unroll
        for (int r = 0; r < 4; ++r) { aS[r][0]=0; aS[r][1]=0; aR[r][0]=0; aR[r][1]=0; }
        #pragma unroll 2
        for (int d = 0; d < 32; ++d) {
            u64 k0 = *(const u64*)&sKT[(hb + d) * 64 + m0];
            u64 k1 = *(const u64*)&sKT[(hb + d) * 64 + m0 + 2];
            u64 e0 = *(const u64*)&sEr[d * 66 + m0];
            u64 e1 = *(const u64*)&sEr[d * 66 + m0 + 2];
            #pragma unroll
            for (int r = 0; r < 4; ++r) {
                u64 q = dup2(sQ[(l0 + r) * 97 + hb + d]);
                fma2(aS[r][0], q, k0); fma2(aS[r][1], q, k1);
                fma2(aR[r][0], q, e0); fma2(aR[r][1], q, e1);
            }
        }
        #pragma unroll
        for (int r = 0; r < 4; ++r) {
            *(u64*)&sS[(l0 + r) * 64 + m0]     = aS[r][0];
            *(u64*)&sS[(l0 + r) * 64 + m0 + 2] = aS[r][1];
            *(u64*)&sR[(l0 + r) * 64 + m0]     = aR[r][0];
            *(u64*)&sR[(l0 + r) * 64 + m0 + 2] = aR[r][1];
        }
        __syncthreads();

        for (int l = wid; l < 64; l += 8) {
            int m1 = lane + 32;
            int j0 = min(lane + 63 - l, 63);
            int j1 = min(m1 + 63 - l, 63);
            float v0 = (lane <= l) ? (sS[l * 64 + lane] + sR[l * 64 + j0]) * scale : -1e30f;
            float v1 = (m1   <= l) ? (sS[l * 64 + m1]   + sR[l * 64 + j1]) * scale : -1e30f;
            float mx = fmaxf(v0, v1);
            #pragma unroll
            for (int o = 16; o; o >>= 1) mx = fmaxf(mx, __shfl_xor_sync(0xffffffffu, mx, o));
            float e0 = __expf(v0 - mx), e1 = __expf(v1 - mx);
            float ssum = e0 + e1;
            #pragma unroll
            for (int o = 16; o; o >>= 1) ssum += __shfl_xor_sync(0xffffffffu, ssum, o);
            float inv = 1.0f / ssum;
            sS[l * 64 + lane] = e0 * inv;
            sS[l * 64 + m1]   = e1 * inv;
        }
        __syncthreads();

        u64 po[4][2];
        #pragma unroll
        for (int r = 0; r < 4; ++r) { po[r][0] = 0; po[r][1] = 0; }
        #pragma unroll 2
        for (int mp = 0; mp < 32; ++mp) {
            u64 v0 = *(const u64*)&sVT[(hb + d0) * 64 + 2 * mp];
            u64 v1 = *(const u64*)&sVT[(hb + d0 + 1) * 64 + 2 * mp];
            #pragma unroll
            for (int r = 0; r < 4; ++r) {
                u64 pv = *(const u64*)&sS[(l0 + r) * 64 + 2 * mp];
                fma2(po[r][0], pv, v0);
                fma2(po[r][1], pv, v1);
            }
        }
        __syncthreads();
        #pragma unroll
        for (int r = 0; r < 4; ++r) {
            sQ[(l0 + r) * 97 + hb + d0]     = hsum2(po[r][0]);
            sQ[(l0 + r) * 97 + hb + d0 + 1] = hsum2(po[r][1]);
        }
    }
    __syncthreads();            // attention done; sKT/sVT/sEr/sS/sR now dead

    // ---- phase B: FFN on this token (att in sQ -> transpose to sX) ----
    for (int idx = tid; idx < 6144; idx += 256) {
        int d = idx >> 6, m = idx & 63;
        sX[d * 68 + m] = sQ[m * 97 + d];
    }

    const int r0 = (tid >> 5) * 8;     // 8 warps x 8 rows = 64
    u64 acc2[4][3];
    #pragma unroll
    for (int i = 0; i < 4; ++i)
        #pragma unroll
        for (int j = 0; j < 3; ++j) acc2[i][j] = 0;

    for (int ch = 0; ch < 6; ++ch) {
        __syncthreads();               // covers transpose on first iter
        for (int idx = tid; idx < 6144; idx += 256) {        // W1 chunk 96x64
            int d = idx >> 6, c = idx & 63;
            sW[idx] = W1[d * 384 + ch * 64 + c];
        }
        __syncthreads();
        u64 ha[4][2];
        #pragma unroll
        for (int i = 0; i < 4; ++i) { ha[i][0] = 0; ha[i][1] = 0; }
        #pragma unroll 2
        for (int d = 0; d < 96; ++d) {
            ulonglong2 a01 = *(const ulonglong2*)&sX[d * 68 + r0];
            ulonglong2 a23 = *(const ulonglong2*)&sX[d * 68 + r0 + 4];
            u64 ap[4] = {a01.x, a01.y, a23.x, a23.y};
            u64 w0 = dup2(sW[d * 64 + lane]);
            u64 w1 = dup2(sW[d * 64 + lane + 32]);
            #pragma unroll
            for (int i = 0; i < 4; ++i) {
                fma2(ha[i][0], ap[i], w0);
                fma2(ha[i][1], ap[i], w1);
            }
        }
        float bb1[2] = {b1[ch * 64 + lane], b1[ch * 64 + lane + 32]};
        #pragma unroll
        for (int i = 0; i < 4; ++i)
            #pragma unroll
            for (int j = 0; j < 2; ++j) {
                float2 p = up2(ha[i][j]);
                int c = lane + 32 * j, row = r0 + 2 * i;
                sH[c * 68 + row]     = fmaxf(p.x + bb1[j], 0.f);
                sH[c * 68 + row + 1] = fmaxf(p.y + bb1[j], 0.f);
            }
        __syncthreads();
        for (int idx = tid; idx < 6144; idx += 256) {        // W2 chunk 64x96
            int k = idx / 96, c = idx - k * 96;
            sW[idx] = W2[(ch * 64 + k) * 96 + c];
        }
        __syncthreads();
        #pragma unroll 2
        for (int k = 0; k < 64; ++k) {
            ulonglong2 a01 = *(const ulonglong2*)&sH[k * 68 + r0];
            ulonglong2 a23 = *(const ulonglong2*)&sH[k * 68 + r0 + 4];
            u64 ap[4] = {a01.x, a01.y, a23.x, a23.y};
            u64 w0 = dup2(sW[k * 96 + lane]);
            u64 w1 = dup2(sW[k * 96 + lane + 32]);
            u64 w2 = dup2(sW[k * 96 + lane + 64]);
            #pragma unroll
            for (int i = 0; i < 4; ++i) {
                fma2(acc2[i][0], ap[i], w0);
                fma2(acc2[i][1], ap[i], w1);
                fma2(acc2[i][2], ap[i], w2);
            }
        }
    }
    __syncthreads();
    float bb2[3] = {b2[lane], b2[lane + 32], b2[lane + 64]};
    #pragma unroll
    for (int i = 0; i < 4; ++i)
        #pragma unroll
        for (int j = 0; j < 3; ++j) {
            float2 p = up2(acc2[i][j]);
            int c = lane + 32 * j, row = r0 + 2 * i;
            sX[c * 68 + row]     = p.x + bb2[j];
            sX[c * 68 + row + 1] = p.y + bb2[j];
        }
    __syncthreads();
    for (int idx = tid; idx < 6144; idx += 256) {
        int c = idx >> 6, m = idx & 63;
        g_mid[base + idx] = sX[c * 68 + m];
    }
}

// ---------------- kernel 3: We GEMM (R8 version — measured best) ------------
#define WBK 32

__global__ __launch_bounds__(256, 3) void we_gemm_kernel(
    const float* __restrict__ We, const float* __restrict__ be)
{
    __shared__ __align__(16) float As[2][WBK * 68];    // [k*68 + m]
    __shared__ __align__(16) float Bs[2][WBK * 128];   // [k*128 + c]
    __shared__ double red[16];

    const int tid = threadIdx.x;
    const int e0 = blockIdx.x * 128;
    const int n0 = blockIdx.y * 64;
    const int r0 = (tid >> 5) * 8;
    const int c0 = (tid & 31) * 4;

    const int am = tid >> 2;
    const int ak = (tid & 3) * 8;

    u64 acc[4][4];
    #pragma unroll
    for (int i = 0; i < 4; ++i)
        #pragma unroll
        for (int j = 0; j < 4; ++j) acc[i][j] = 0;

    float4 ra0, ra1;
    const float* arow = &g_mid[(size_t)(n0 + am) * Fc + ak];

    ra0 = *(const float4*)(arow);
    ra1 = *(const float4*)(arow + 4);
    #pragma unroll
    for (int q = 0; q < 4; ++q) {
        int lin = tid + q * 256;
        int k = lin >> 5, c4 = (lin & 31) * 4;
        cp16(&Bs[0][k * 128 + c4], &We[(size_t)k * EMBc + e0 + c4]);
    }
    cp_commit();
    {
        float* a = &As[0][ak * 68 + am];
        a[0] = ra0.x; a[68] = ra0.y; a[136] = ra0.z; a[204] = ra0.w;
        a[272] = ra1.x; a[340] = ra1.y; a[408] = ra1.z; a[476] = ra1.w;
    }

    const int NT = Fc / WBK;            // 192
    for (int t = 0; t < NT; ++t) {
        const int b = t & 1;
        if (t + 1 < NT) {
            ra0 = *(const float4*)(arow + (t + 1) * WBK);
            ra1 = *(const float4*)(arow + (t + 1) * WBK + 4);
            #pragma unroll
            for (int q = 0; q < 4; ++q) {
                int lin = tid + q * 256;
                int k = lin >> 5, c4 = (lin & 31) * 4;
                cp16(&Bs[b ^ 1][k * 128 + c4],
                     &We[(size_t)((t + 1) * WBK + k) * EMBc + e0 + c4]);
            }
            cp_commit();
            cp_wait<1>();
        } else {
            cp_wait<0>();
        }
        __syncthreads();

        #pragma unroll
        for (int k = 0; k < WBK; ++k) {
            ulonglong2 a01 = *(const ulonglong2*)&As[b][k * 68 + r0];
            ulonglong2 a23 = *(const ulonglong2*)&As[b][k * 68 + r0 + 4];
            u64 ap[4] = {a01.x, a01.y, a23.x, a23.y};
            float4 bv = *(const float4*)&Bs[b][k * 128 + c0];
            u64 bd[4] = {dup2(bv.x), dup2(bv.y), dup2(bv.z), dup2(bv.w)};
            #pragma unroll
            for (int i = 0; i < 4; ++i)
                #pragma unroll
                for (int j = 0; j < 4; ++j) fma2(acc[i][j], ap[i], bd[j]);
        }
        __syncthreads();
        if (t + 1 < NT) {
            float* a = &As[b ^ 1][ak * 68 + am];
            a[0] = ra0.x; a[68] = ra0.y; a[136] = ra0.z; a[204] = ra0.w;
            a[272] = ra1.x; a[340] = ra1.y; a[408] = ra1.z; a[476] = ra1.w;
        }
    }

    float beb[4];
    #pragma unroll
    for (int j = 0; j < 4; ++j) beb[j] = be[e0 + c0 + j];

    double s = 0.0, s2 = 0.0;
    #pragma unroll
    for (int i = 0; i < 4; ++i) {
        float4 o0, o1;
        float2 p0 = up2(acc[i][0]), p1 = up2(acc[i][1]);
        float2 p2 = up2(acc[i][2]), p3 = up2(acc[i][3]);
        o0.x = p0.x + beb[0]; o0.y = p1.x + beb[1]; o0.z = p2.x + beb[2]; o0.w = p3.x + beb[3];
        o1.x = p0.y + beb[0]; o1.y = p1.y + beb[1]; o1.z = p2.y + beb[2]; o1.w = p3.y + beb[3];
        int row0 = n0 + r0 + 2 * i;
        *(float4*)&g_emb[(size_t)row0 * EMBc + e0 + c0]       = o0;
        *(float4*)&g_emb[(size_t)(row0 + 1) * EMBc + e0 + c0] = o1;
        s  += (double)o0.x + o0.y + o0.z + o0.w + (double)o1.x + o1.y + o1.z + o1.w;
        s2 += (double)o0.x * o0.x + (double)o0.y * o0.y + (double)o0.z * o0.z + (double)o0.w * o0.w
            + (double)o1.x * o1.x + (double)o1.y * o1.y + (double)o1.z * o1.z + (double)o1.w * o1.w;
    }
    #pragma unroll
    for (int o = 16; o; o >>= 1) {
        s  += __shfl_xor_sync(0xffffffffu, s, o);
        s2 += __shfl_xor_sync(0xffffffffu, s2, o);
    }
    const int wrp = tid >> 5, lane = tid & 31;
    if (lane == 0) { red[wrp] = s; red[wrp + 8] = s2; }
    __syncthreads();
    if (tid == 0) {
        double ts = 0.0, ts2 = 0.0;
        #pragma unroll
        for (int i = 0; i < 8; ++i) { ts += red[i]; ts2 += red[i + 8]; }
        int bid = blockIdx.y * gridDim.x + blockIdx.x;   // < 256
        g_part[bid * 2]     = ts;
        g_part[bid * 2 + 1] = ts2;
    }
}

// ---------------- kernel 4: finalize mean / rstd ----------------------------
__global__ void stats_kernel()
{
    if (threadIdx.x == 0) {
        double s = 0.0, s2 = 0.0;
        for (int i = 0; i < 256; ++i) { s += g_part[2 * i]; s2 += g_part[2 * i + 1]; }
        double cnt = (double)NTOK * (double)EMBc;
        double mu  = s / cnt;
        double var = s2 / cnt - mu * mu;
        g_stats[0] = (float)mu;
        g_stats[1] = (float)(1.0 / sqrt(var + 1e-8));
    }
}

// ---------------- kernel 5: normalize + segment means + residual ------------
__global__ __launch_bounds__(256) void final_kernel(
    const int* __restrict__ o_enc, const float* __restrict__ r_enc,
    float* __restrict__ out)
{
    const int n = blockIdx.x;
    const int b = n >> 10, t = n & 1023;
    __shared__ int s_len;
    if (threadIdx.x == 0) {
        int len = 0;
        bool is_start = (t == 0) || (o_enc[n] != 0);
        if (is_start) {
            int tt = t + 1;
            while (tt < TT && o_enc[b * TT + tt] == 0) ++tt;
            len = tt - t;
        }
        s_len = len;
    }
    __syncthreads();
    const float mu = g_stats[0], rs = g_stats[1];
    const int len = s_len;
    for (int e = threadIdx.x; e < EMBc; e += 256) {
        size_t bi = (size_t)n * EMBc + e;
        float v = (g_emb[bi] - mu) * rs;
        float o = v + r_enc[bi];
        if (len) {
            float sum = 0.f;
            for (int s = 0; s < len; ++s)
                sum += g_emb[(size_t)(n + s) * EMBc + e];
            o += (sum / (float)len - mu) * rs;
        }
        out[bi] = o;
    }
}

// ---------------- launcher --------------------------------------------------
extern "C" void kernel_launch(void* const* d_in, const int* in_sizes, int n_in,
                              void* d_out, int out_size)
{
    const float* x     = (const float*)d_in[0];
    const int*   o_enc = (const int*)  d_in[1];
    const float* r_enc = (const float*)d_in[2];
    const float* Wq    = (const float*)d_in[3];
    const float* bq    = (const float*)d_in[4];
    const float* Wk    = (const float*)d_in[5];
    const float* bk    = (const float*)d_in[6];
    const float* Wv    = (const float*)d_in[7];
    const float* bv    = (const float*)d_in[8];
    const float* Er    = (const float*)d_in[9];
    const float* W1    = (const float*)d_in[10];
    const float* b1    = (const float*)d_in[11];
    const float* W2    = (const float*)d_in[12];
    const float* b2    = (const float*)d_in[13];
    const float* We    = (const float*)d_in[14];
    const float* be    = (const float*)d_in[15];
    float* out = (float*)d_out;

    cudaFuncSetAttribute(qkv_kernel, cudaFuncAttributeMaxDynamicSharedMemorySize,
                         QKV_SMEM * 4);
    cudaFuncSetAttribute(attn_ffn_kernel, cudaFuncAttributeMaxDynamicSharedMemorySize,
                         ATT_SMEM * 4);

    qkv_kernel<<<dim3(NTOK / 2, 3), 512, QKV_SMEM * 4>>>(x, Wq, bq, Wk, bk, Wv, bv);

    attn_ffn_kernel<<<NTOK, 256, ATT_SMEM * 4>>>(Er, W1, b1, W2, b2);

    dim3 g2(EMBc / 128, NTOK / 64);    // (4, 64) = 256 blocks
    we_gemm_kernel<<<g2, 256>>>(We, be);

    stats_kernel<<<1, 32>>>();

    final_kernel<<<NTOK, 256>>>(o_enc, r_enc, out);
}

// round 17
// speedup vs baseline: 1.0353x; 1.0353x over previous
#include <cuda_runtime.h>
#include <math.h>

#define NTOK 4096          // B*T
#define TT   1024
#define Fc   6144          // SW*FB = 96*64
#define EMBc 512

typedef unsigned long long u64;

// ---------------- packed f32x2 helpers (FFMA2 path) -------------------------
__device__ __forceinline__ void fma2(u64 &d, u64 a, u64 b) {
    asm("fma.rn.f32x2 %0, %1, %2, %0;" : "+l"(d) : "l"(a), "l"(b));
}
__device__ __forceinline__ u64 dup2(float x) {
    u64 r; asm("mov.b64 %0, {%1, %1};" : "=l"(r) : "f"(x)); return r;
}
__device__ __forceinline__ float2 up2(u64 v) {
    float2 p; asm("mov.b64 {%0, %1}, %2;" : "=f"(p.x), "=f"(p.y) : "l"(v)); return p;
}
__device__ __forceinline__ float hsum2(u64 v) { float2 p = up2(v); return p.x + p.y; }

// ---------------- cp.async helpers ------------------------------------------
__device__ __forceinline__ void cp16(void* s, const void* g) {
    unsigned sa = (unsigned)__cvta_generic_to_shared(s);
    asm volatile("cp.async.cg.shared.global [%0], [%1], 16;" :: "r"(sa), "l"(g));
}
__device__ __forceinline__ void cp_commit() {
    asm volatile("cp.async.commit_group;");
}
template<int N> __device__ __forceinline__ void cp_wait() {
    asm volatile("cp.async.wait_group %0;" :: "n"(N));
}

// ---------------- scratch ---------------------------------------------------
__device__ float  g_q[(size_t)NTOK * Fc];     // [(n,l), d]
__device__ float  g_kT[(size_t)NTOK * Fc];    // [n][d][m]
__device__ float  g_vT[(size_t)NTOK * Fc];    // [n][d][m]
__device__ float  g_attT[(size_t)NTOK * Fc];  // [n][d][l]
__device__ float  g_mid[(size_t)NTOK * Fc];   // (B,T,F)
__device__ float  g_emb[(size_t)NTOK * EMBc];
__device__ double g_part[512];                // 256 blocks * 2
__device__ float  g_stats[2];

// ---------------- kernel 1: batched QKV GEMM --------------------------------
#define QKV_SMEM (12416 + 9216)

__global__ __launch_bounds__(512, 2) void qkv_kernel(
    const float* __restrict__ x,
    const float* __restrict__ Wq, const float* __restrict__ bq,
    const float* __restrict__ Wk, const float* __restrict__ bk,
    const float* __restrict__ Wv, const float* __restrict__ bv)
{
    extern __shared__ float sm[];
    float* As = sm;
    float* Ws = sm + 12416;

    const int tid = threadIdx.x;
    const int mat = blockIdx.y;
    const int n0  = blockIdx.x * 2;
    const size_t xbase = (size_t)n0 * Fc;

    const float* W  = (mat == 0) ? Wq : (mat == 1) ? Wk : Wv;
    const float* bi = (mat == 0) ? bq : (mat == 1) ? bk : bv;

    for (int idx = tid; idx < 12288; idx += 512) {
        int d = idx >> 7, m = idx & 127;
        As[idx] = x[xbase + (size_t)(m >> 6) * Fc + d * 64 + (m & 63)];
    }
    for (int idx = tid; idx < 9216; idx += 512) Ws[idx] = W[idx];
    __syncthreads();

    const int r0 = (tid >> 5) * 8;
    const int lane = tid & 31;
    u64 acc[4][3];
    #pragma unroll
    for (int i = 0; i < 4; ++i)
        #pragma unroll
        for (int j = 0; j < 3; ++j) acc[i][j] = 0;

    #pragma unroll 2
    for (int d = 0; d < 96; ++d) {
        ulonglong2 a01 = *(const ulonglong2*)&As[d * 128 + r0];
        ulonglong2 a23 = *(const ulonglong2*)&As[d * 128 + r0 + 4];
        u64 ap[4] = {a01.x, a01.y, a23.x, a23.y};
        u64 w0 = dup2(Ws[d * 96 + lane]);
        u64 w1 = dup2(Ws[d * 96 + lane + 32]);
        u64 w2 = dup2(Ws[d * 96 + lane + 64]);
        #pragma unroll
        for (int i = 0; i < 4; ++i) {
            fma2(acc[i][0], ap[i], w0);
            fma2(acc[i][1], ap[i], w1);
            fma2(acc[i][2], ap[i], w2);
        }
    }
    float bb[3] = {bi[lane], bi[lane + 32], bi[lane + 64]};

    if (mat == 0) {
        #pragma unroll
        for (int i = 0; i < 4; ++i)
            #pragma unroll
            for (int j = 0; j < 3; ++j) {
                float2 p = up2(acc[i][j]);
                int row = r0 + 2 * i, col = lane + 32 * j;
                g_q[xbase + (size_t)row * 96 + col]       = p.x + bb[j];
                g_q[xbase + (size_t)(row + 1) * 96 + col] = p.y + bb[j];
            }
    } else {
        __syncthreads();
        #pragma unroll
        for (int i = 0; i < 4; ++i)
            #pragma unroll
            for (int j = 0; j < 3; ++j) {
                float2 p = up2(acc[i][j]);
                int col = lane + 32 * j, row = r0 + 2 * i;
                As[col * 129 + row]     = p.x + bb[j];
                As[col * 129 + row + 1] = p.y + bb[j];
            }
        __syncthreads();
        float* gout = (mat == 1) ? g_kT : g_vT;
        for (int idx = tid; idx < 12288; idx += 512) {
            int d = idx >> 7, m = idx & 127;
            gout[xbase + (size_t)(m >> 6) * Fc + d * 64 + (m & 63)] = As[d * 129 + m];
        }
    }
}

// ---------------- kernel 2: per-token attention (float4 ingest) -------------
#define ATT_SMEM 28800

__global__ __launch_bounds__(256, 2) void attn_kernel(const float* __restrict__ Er)
{
    extern __shared__ float sm[];
    float* sQ  = sm;             // [l*97 + d]
    float* sKT = sm + 6208;      // [d*64 + m]
    float* sVT = sKT + 6144;     // [d*64 + m]
    float* sEr = sVT + 6144;     // [d*66 + j]
    float* sS  = sEr + 2112;     // [l*64 + m]
    float* sR  = sS + 4096;      // [l*64 + j]

    const int tid = threadIdx.x;
    const int n   = blockIdx.x;
    const size_t base = (size_t)n * Fc;

    // vectorized ingest: q rows are 96 floats (24 float4) -> conflict-free scatter
    for (int i4 = tid; i4 < 1536; i4 += 256) {
        float4 v = *(const float4*)&g_q[base + (size_t)i4 * 4];
        int idx = i4 * 4;
        int l = idx / 96, d = idx - l * 96;
        sQ[l * 97 + d]     = v.x;
        sQ[l * 97 + d + 1] = v.y;
        sQ[l * 97 + d + 2] = v.z;
        sQ[l * 97 + d + 3] = v.w;
    }
    for (int i4 = tid; i4 < 1536; i4 += 256)
        *(float4*)&sKT[i4 * 4] = *(const float4*)&g_kT[base + (size_t)i4 * 4];
    for (int i4 = tid; i4 < 1536; i4 += 256)
        *(float4*)&sVT[i4 * 4] = *(const float4*)&g_vT[base + (size_t)i4 * 4];
    for (int idx = tid; idx < 2048; idx += 256) {
        int j = idx >> 5, d = idx & 31;
        sEr[d * 66 + j] = Er[idx];
    }
    __syncthreads();

    const float scale = 0.17677669529663687f;
    const int wid = tid >> 5, lane = tid & 31;
    const int l0 = (tid >> 4) * 4, m0 = (tid & 15) * 4;
    const int d0 = (tid & 15) * 2;

    for (int h = 0; h < 3; ++h) {
        const int hb = h * 32;
        u64 aS[4][2], aR[4][2];
        #pragma unroll
        for (int r = 0; r < 4; ++r) { aS[r][0]=0; aS[r][1]=0; aR[r][0]=0; aR[r][1]=0; }
        #pragma unroll 2
        for (int d = 0; d < 32; ++d) {
            u64 k0 = *(const u64*)&sKT[(hb + d) * 64 + m0];
            u64 k1 = *(const u64*)&sKT[(hb + d) * 64 + m0 + 2];
            u64 e0 = *(const u64*)&sEr[d * 66 + m0];
            u64 e1 = *(const u64*)&sEr[d * 66 + m0 + 2];
            #pragma unroll
            for (int r = 0; r < 4; ++r) {
                u64 q = dup2(sQ[(l0 + r) * 97 + hb + d]);
                fma2(aS[r][0], q, k0); fma2(aS[r][1], q, k1);
                fma2(aR[r][0], q, e0); fma2(aR[r][1], q, e1);
            }
        }
        #pragma unroll
        for (int r = 0; r < 4; ++r) {
            *(u64*)&sS[(l0 + r) * 64 + m0]     = aS[r][0];
            *(u64*)&sS[(l0 + r) * 64 + m0 + 2] = aS[r][1];
            *(u64*)&sR[(l0 + r) * 64 + m0]     = aR[r][0];
            *(u64*)&sR[(l0 + r) * 64 + m0 + 2] = aR[r][1];
        }
        __syncthreads();

        for (int l = wid; l < 64; l += 8) {
            int m1 = lane + 32;
            int j0 = min(lane + 63 - l, 63);
            int j1 = min(m1 + 63 - l, 63);
            float v0 = (lane <= l) ? (sS[l * 64 + lane] + sR[l * 64 + j0]) * scale : -1e30f;
            float v1 = (m1   <= l) ? (sS[l * 64 + m1]   + sR[l * 64 + j1]) * scale : -1e30f;
            float mx = fmaxf(v0, v1);
            #pragma unroll
            for (int o = 16; o; o >>= 1) mx = fmaxf(mx, __shfl_xor_sync(0xffffffffu, mx, o));
            float e0 = __expf(v0 - mx), e1 = __expf(v1 - mx);
            float ssum = e0 + e1;
            #pragma unroll
            for (int o = 16; o; o >>= 1) ssum += __shfl_xor_sync(0xffffffffu, ssum, o);
            float inv = 1.0f / ssum;
            sS[l * 64 + lane] = e0 * inv;
            sS[l * 64 + m1]   = e1 * inv;
        }
        __syncthreads();

        u64 po[4][2];
        #pragma unroll
        for (int r = 0; r < 4; ++r) { po[r][0] = 0; po[r][1] = 0; }
        #pragma unroll 2
        for (int mp = 0; mp < 32; ++mp) {
            u64 v0 = *(const u64*)&sVT[(hb + d0) * 64 + 2 * mp];
            u64 v1 = *(const u64*)&sVT[(hb + d0 + 1) * 64 + 2 * mp];
            #pragma unroll
            for (int r = 0; r < 4; ++r) {
                u64 pv = *(const u64*)&sS[(l0 + r) * 64 + 2 * mp];
                fma2(po[r][0], pv, v0);
                fma2(po[r][1], pv, v1);
            }
        }
        __syncthreads();
        #pragma unroll
        for (int r = 0; r < 4; ++r) {
            sQ[(l0 + r) * 97 + hb + d0]     = hsum2(po[r][0]);
            sQ[(l0 + r) * 97 + hb + d0 + 1] = hsum2(po[r][1]);
        }
    }
    __syncthreads();
    for (int idx = tid; idx < Fc; idx += 256) {
        int d = idx >> 6, l = idx & 63;
        g_attT[base + idx] = sQ[l * 97 + d];
    }
}

// ---------------- kernel 3: fused FFN (R8 version — measured best) ----------
// smem: sX 12672 | sW 6144 | sH 64*132=8448  = 27264 floats (109 KB)
#define FFN_SMEM (12672 + 6144 + 8448)

__global__ __launch_bounds__(512, 2) void ffn_kernel(
    const float* __restrict__ W1, const float* __restrict__ b1,
    const float* __restrict__ W2, const float* __restrict__ b2)
{
    extern __shared__ float sm[];
    float* sX = sm;            // att tile [d*132 + m]; reused as out bounce
    float* sW = sm + 12672;    // W1 chunk [d*64+c] / W2 chunk [k*96+c]
    float* sH = sW + 6144;     // h chunk [c*132 + m], c in [0,64)

    const int tid = threadIdx.x;
    const int n0  = blockIdx.x * 2;
    const size_t base = (size_t)n0 * Fc;

    for (int idx = tid; idx < 12288; idx += 512) {
        int d = idx >> 7, m = idx & 127;
        sX[d * 132 + m] = g_attT[base + (size_t)(m >> 6) * Fc + d * 64 + (m & 63)];
    }

    const int r0 = (tid >> 5) * 8;
    const int lane = tid & 31;
    u64 acc2[4][3];
    #pragma unroll
    for (int i = 0; i < 4; ++i)
        #pragma unroll
        for (int j = 0; j < 3; ++j) acc2[i][j] = 0;

    for (int ch = 0; ch < 6; ++ch) {
        __syncthreads();
        for (int idx = tid; idx < 6144; idx += 512) {        // W1 chunk 96x64
            int d = idx >> 6, c = idx & 63;
            sW[idx] = W1[d * 384 + ch * 64 + c];
        }
        __syncthreads();
        u64 ha[4][2];
        #pragma unroll
        for (int i = 0; i < 4; ++i) { ha[i][0] = 0; ha[i][1] = 0; }
        #pragma unroll 2
        for (int d = 0; d < 96; ++d) {
            ulonglong2 a01 = *(const ulonglong2*)&sX[d * 132 + r0];
            ulonglong2 a23 = *(const ulonglong2*)&sX[d * 132 + r0 + 4];
            u64 ap[4] = {a01.x, a01.y, a23.x, a23.y};
            u64 w0 = dup2(sW[d * 64 + lane]);
            u64 w1 = dup2(sW[d * 64 + lane + 32]);
            #pragma unroll
            for (int i = 0; i < 4; ++i) {
                fma2(ha[i][0], ap[i], w0);
                fma2(ha[i][1], ap[i], w1);
            }
        }
        float bb1[2] = {b1[ch * 64 + lane], b1[ch * 64 + lane + 32]};
        #pragma unroll
        for (int i = 0; i < 4; ++i)
            #pragma unroll
            for (int j = 0; j < 2; ++j) {
                float2 p = up2(ha[i][j]);
                int c = lane + 32 * j, row = r0 + 2 * i;
                sH[c * 132 + row]     = fmaxf(p.x + bb1[j], 0.f);
                sH[c * 132 + row + 1] = fmaxf(p.y + bb1[j], 0.f);
            }
        __syncthreads();
        for (int idx = tid; idx < 6144; idx += 512) {        // W2 chunk 64x96
            int k = idx / 96, c = idx - k * 96;
            sW[idx] = W2[(ch * 64 + k) * 96 + c];
        }
        __syncthreads();
        #pragma unroll 2
        for (int k = 0; k < 64; ++k) {
            ulonglong2 a01 = *(const ulonglong2*)&sH[k * 132 + r0];
            ulonglong2 a23 = *(const ulonglong2*)&sH[k * 132 + r0 + 4];
            u64 ap[4] = {a01.x, a01.y, a23.x, a23.y};
            u64 w0 = dup2(sW[k * 96 + lane]);
            u64 w1 = dup2(sW[k * 96 + lane + 32]);
            u64 w2 = dup2(sW[k * 96 + lane + 64]);
            #pragma unroll
            for (int i = 0; i < 4; ++i) {
                fma2(acc2[i][0], ap[i], w0);
                fma2(acc2[i][1], ap[i], w1);
                fma2(acc2[i][2], ap[i], w2);
            }
        }
    }
    __syncthreads();
    float bb2[3] = {b2[lane], b2[lane + 32], b2[lane + 64]};
    #pragma unroll
    for (int i = 0; i < 4; ++i)
        #pragma unroll
        for (int j = 0; j < 3; ++j) {
            float2 p = up2(acc2[i][j]);
            int c = lane + 32 * j, row = r0 + 2 * i;
            sX[c * 132 + row]     = p.x + bb2[j];
            sX[c * 132 + row + 1] = p.y + bb2[j];
        }
    __syncthreads();
    for (int idx = tid; idx < 12288; idx += 512) {
        int c = idx >> 7, m = idx & 127;
        g_mid[base + (size_t)(m >> 6) * Fc + c * 64 + (m & 63)] = sX[c * 132 + m];
    }
}

// ---------------- kernel 4: We GEMM (R8 version — measured best) ------------
#define WBK 32

__global__ __launch_bounds__(256, 3) void we_gemm_kernel(
    const float* __restrict__ We, const float* __restrict__ be)
{
    __shared__ __align__(16) float As[2][WBK * 68];    // [k*68 + m]
    __shared__ __align__(16) float Bs[2][WBK * 128];   // [k*128 + c]
    __shared__ double red[16];

    const int tid = threadIdx.x;
    const int e0 = blockIdx.x * 128;
    const int n0 = blockIdx.y * 64;
    const int r0 = (tid >> 5) * 8;
    const int c0 = (tid & 31) * 4;

    const int am = tid >> 2;
    const int ak = (tid & 3) * 8;

    u64 acc[4][4];
    #pragma unroll
    for (int i = 0; i < 4; ++i)
        #pragma unroll
        for (int j = 0; j < 4; ++j) acc[i][j] = 0;

    float4 ra0, ra1;
    const float* arow = &g_mid[(size_t)(n0 + am) * Fc + ak];

    ra0 = *(const float4*)(arow);
    ra1 = *(const float4*)(arow + 4);
    #pragma unroll
    for (int q = 0; q < 4; ++q) {
        int lin = tid + q * 256;
        int k = lin >> 5, c4 = (lin & 31) * 4;
        cp16(&Bs[0][k * 128 + c4], &We[(size_t)k * EMBc + e0 + c4]);
    }
    cp_commit();
    {
        float* a = &As[0][ak * 68 + am];
        a[0] = ra0.x; a[68] = ra0.y; a[136] = ra0.z; a[204] = ra0.w;
        a[272] = ra1.x; a[340] = ra1.y; a[408] = ra1.z; a[476] = ra1.w;
    }

    const int NT = Fc / WBK;            // 192
    for (int t = 0; t < NT; ++t) {
        const int b = t & 1;
        if (t + 1 < NT) {
            ra0 = *(const float4*)(arow + (t + 1) * WBK);
            ra1 = *(const float4*)(arow + (t + 1) * WBK + 4);
            #pragma unroll
            for (int q = 0; q < 4; ++q) {
                int lin = tid + q * 256;
                int k = lin >> 5, c4 = (lin & 31) * 4;
                cp16(&Bs[b ^ 1][k * 128 + c4],
                     &We[(size_t)((t + 1) * WBK + k) * EMBc + e0 + c4]);
            }
            cp_commit();
            cp_wait<1>();
        } else {
            cp_wait<0>();
        }
        __syncthreads();

        #pragma unroll
        for (int k = 0; k < WBK; ++k) {
            ulonglong2 a01 = *(const ulonglong2*)&As[b][k * 68 + r0];
            ulonglong2 a23 = *(const ulonglong2*)&As[b][k * 68 + r0 + 4];
            u64 ap[4] = {a01.x, a01.y, a23.x, a23.y};
            float4 bv = *(const float4*)&Bs[b][k * 128 + c0];
            u64 bd[4] = {dup2(bv.x), dup2(bv.y), dup2(bv.z), dup2(bv.w)};
            #pragma unroll
            for (int i = 0; i < 4; ++i)
                #pragma unroll
                for (int j = 0; j < 4; ++j) fma2(acc[i][j], ap[i], bd[j]);
        }
        __syncthreads();
        if (t + 1 < NT) {
            float* a = &As[b ^ 1][ak * 68 + am];
            a[0] = ra0.x; a[68] = ra0.y; a[136] = ra0.z; a[204] = ra0.w;
            a[272] = ra1.x; a[340] = ra1.y; a[408] = ra1.z; a[476] = ra1.w;
        }
    }

    float beb[4];
    #pragma unroll
    for (int j = 0; j < 4; ++j) beb[j] = be[e0 + c0 + j];

    double s = 0.0, s2 = 0.0;
    #pragma unroll
    for (int i = 0; i < 4; ++i) {
        float4 o0, o1;
        float2 p0 = up2(acc[i][0]), p1 = up2(acc[i][1]);
        float2 p2 = up2(acc[i][2]), p3 = up2(acc[i][3]);
        o0.x = p0.x + beb[0]; o0.y = p1.x + beb[1]; o0.z = p2.x + beb[2]; o0.w = p3.x + beb[3];
        o1.x = p0.y + beb[0]; o1.y = p1.y + beb[1]; o1.z = p2.y + beb[2]; o1.w = p3.y + beb[3];
        int row0 = n0 + r0 + 2 * i;
        *(float4*)&g_emb[(size_t)row0 * EMBc + e0 + c0]       = o0;
        *(float4*)&g_emb[(size_t)(row0 + 1) * EMBc + e0 + c0] = o1;
        s  += (double)o0.x + o0.y + o0.z + o0.w + (double)o1.x + o1.y + o1.z + o1.w;
        s2 += (double)o0.x * o0.x + (double)o0.y * o0.y + (double)o0.z * o0.z + (double)o0.w * o0.w
            + (double)o1.x * o1.x + (double)o1.y * o1.y + (double)o1.z * o1.z + (double)o1.w * o1.w;
    }
    #pragma unroll
    for (int o = 16; o; o >>= 1) {
        s  += __shfl_xor_sync(0xffffffffu, s, o);
        s2 += __shfl_xor_sync(0xffffffffu, s2, o);
    }
    const int wrp = tid >> 5, lane = tid & 31;
    if (lane == 0) { red[wrp] = s; red[wrp + 8] = s2; }
    __syncthreads();
    if (tid == 0) {
        double ts = 0.0, ts2 = 0.0;
        #pragma unroll
        for (int i = 0; i < 8; ++i) { ts += red[i]; ts2 += red[i + 8]; }
        int bid = blockIdx.y * gridDim.x + blockIdx.x;   // < 256
        g_part[bid * 2]     = ts;
        g_part[bid * 2 + 1] = ts2;
    }
}

// ---------------- kernel 5: finalize mean / rstd (parallel) -----------------
__global__ __launch_bounds__(256) void stats_kernel()
{
    __shared__ double red[16];
    const int tid = threadIdx.x;
    double s  = g_part[2 * tid];
    double s2 = g_part[2 * tid + 1];
    #pragma unroll
    for (int o = 16; o; o >>= 1) {
        s  += __shfl_xor_sync(0xffffffffu, s, o);
        s2 += __shfl_xor_sync(0xffffffffu, s2, o);
    }
    const int wrp = tid >> 5, lane = tid & 31;
    if (lane == 0) { red[wrp] = s; red[wrp + 8] = s2; }
    __syncthreads();
    if (tid == 0) {
        double ts = 0.0, ts2 = 0.0;
        #pragma unroll
        for (int i = 0; i < 8; ++i) { ts += red[i]; ts2 += red[i + 8]; }
        double cnt = (double)NTOK * (double)EMBc;
        double mu  = ts / cnt;
        double var = ts2 / cnt - mu * mu;
        g_stats[0] = (float)mu;
        g_stats[1] = (float)(1.0 / sqrt(var + 1e-8));
    }
}

// ---------------- kernel 6: normalize + segment means + residual ------------
__global__ __launch_bounds__(256) void final_kernel(
    const int* __restrict__ o_enc, const float* __restrict__ r_enc,
    float* __restrict__ out)
{
    const int n = blockIdx.x;
    const int b = n >> 10, t = n & 1023;
    __shared__ int s_len;
    if (threadIdx.x == 0) {
        int len = 0;
        bool is_start = (t == 0) || (o_enc[n] != 0);
        if (is_start) {
            int tt = t + 1;
            while (tt < TT && o_enc[b * TT + tt] == 0) ++tt;
            len = tt - t;
        }
        s_len = len;
    }
    __syncthreads();
    const float mu = g_stats[0], rs = g_stats[1];
    const int len = s_len;
    for (int e = threadIdx.x; e < EMBc; e += 256) {
        size_t bi = (size_t)n * EMBc + e;
        float v = (g_emb[bi] - mu) * rs;
        float o = v + r_enc[bi];
        if (len) {
            float sum = 0.f;
            for (int s = 0; s < len; ++s)
                sum += g_emb[(size_t)(n + s) * EMBc + e];
            o += (sum / (float)len - mu) * rs;
        }
        out[bi] = o;
    }
}

// ---------------- launcher --------------------------------------------------
extern "C" void kernel_launch(void* const* d_in, const int* in_sizes, int n_in,
                              void* d_out, int out_size)
{
    const float* x     = (const float*)d_in[0];
    const int*   o_enc = (const int*)  d_in[1];
    const float* r_enc = (const float*)d_in[2];
    const float* Wq    = (const float*)d_in[3];
    const float* bq    = (const float*)d_in[4];
    const float* Wk    = (const float*)d_in[5];
    const float* bk    = (const float*)d_in[6];
    const float* Wv    = (const float*)d_in[7];
    const float* bv    = (const float*)d_in[8];
    const float* Er    = (const float*)d_in[9];
    const float* W1    = (const float*)d_in[10];
    const float* b1    = (const float*)d_in[11];
    const float* W2    = (const float*)d_in[12];
    const float* b2    = (const float*)d_in[13];
    const float* We    = (const float*)d_in[14];
    const float* be    = (const float*)d_in[15];
    float* out = (float*)d_out;

    cudaFuncSetAttribute(qkv_kernel, cudaFuncAttributeMaxDynamicSharedMemorySize,
                         QKV_SMEM * 4);
    cudaFuncSetAttribute(attn_kernel, cudaFuncAttributeMaxDynamicSharedMemorySize,
                         ATT_SMEM * 4);
    cudaFuncSetAttribute(ffn_kernel, cudaFuncAttributeMaxDynamicSharedMemorySize,
                         FFN_SMEM * 4);

    qkv_kernel<<<dim3(NTOK / 2, 3), 512, QKV_SMEM * 4>>>(x, Wq, bq, Wk, bk, Wv, bv);

    attn_kernel<<<NTOK, 256, ATT_SMEM * 4>>>(Er);

    ffn_kernel<<<NTOK / 2, 512, FFN_SMEM * 4>>>(W1, b1, W2, b2);

    dim3 g2(EMBc / 128, NTOK / 64);    // (4, 64) = 256 blocks
    we_gemm_kernel<<<g2, 256>>>(We, be);

    stats_kernel<<<1, 256>>>();

    final_kernel<<<NTOK, 256>>>(o_enc, r_enc, out);
}